// round 1
// baseline (speedup 1.0000x reference)
#include <cuda_runtime.h>
#include <cuda_bf16.h>
#include <cstdint>

#define B_ 512
#define T_ 8
#define D_ 512
#define H_ 512
#define LAT_ 64
#define H2_ 1024
#define H3_ 1536

// ---------------- persistent device scratch (static, no allocation) ----------------
__device__ __align__(16) float g_h[B_ * H_];
__device__ __align__(16) float g_hin[B_ * H_];
__device__ __align__(16) float g_kacc[B_ * H_];
__device__ __align__(16) float g_a1[B_ * H2_];
__device__ __align__(16) float g_a2[B_ * H2_];
__device__ __align__(16) float g_gh[B_ * H3_];
__device__ __align__(16) float g_gi[B_ * T_ * H3_];
__device__ __align__(16) float g_t0[B_ * T_];
__device__ __align__(16) float g_dt[B_ * T_];
__device__ __align__(16) float g_w1t[H2_];

__device__ __align__(16) __nv_bfloat16 g_W1hi[H2_ * H_];
__device__ __align__(16) __nv_bfloat16 g_W1lo[H2_ * H_];
__device__ __align__(16) __nv_bfloat16 g_W2hi[H2_ * H2_];
__device__ __align__(16) __nv_bfloat16 g_W2lo[H2_ * H2_];
__device__ __align__(16) __nv_bfloat16 g_W3hi[H_ * H2_];
__device__ __align__(16) __nv_bfloat16 g_W3lo[H_ * H2_];
__device__ __align__(16) __nv_bfloat16 g_Wihhi[H3_ * D_];
__device__ __align__(16) __nv_bfloat16 g_Wihlo[H3_ * D_];
__device__ __align__(16) __nv_bfloat16 g_Whhhi[H3_ * H_];
__device__ __align__(16) __nv_bfloat16 g_Whhlo[H3_ * H_];
__device__ __align__(16) __nv_bfloat16 g_Wouthi[2 * LAT_ * H_];
__device__ __align__(16) __nv_bfloat16 g_Woutlo[2 * LAT_ * H_];

// ---------------- small prep kernels ----------------
__global__ void k_split(const float* __restrict__ src, __nv_bfloat16* __restrict__ hi,
                        __nv_bfloat16* __restrict__ lo, int n) {
    int i = blockIdx.x * blockDim.x + threadIdx.x;
    if (i >= n) return;
    float v = src[i];
    __nv_bfloat16 h = __float2bfloat16(v);
    hi[i] = h;
    lo[i] = __float2bfloat16(v - __bfloat162float(h));
}

// W1 is (H2_, H_+1): split first H_ columns, keep last column fp32 (t coefficient)
__global__ void k_split_w1(const float* __restrict__ W1) {
    int i = blockIdx.x * blockDim.x + threadIdx.x;
    if (i < H2_ * H_) {
        int r = i >> 9, c = i & (H_ - 1);
        float v = W1[r * (H_ + 1) + c];
        __nv_bfloat16 h = __float2bfloat16(v);
        g_W1hi[i] = h;
        g_W1lo[i] = __float2bfloat16(v - __bfloat162float(h));
    }
    if (i < H2_) g_w1t[i] = W1[i * (H_ + 1) + H_];
}

__global__ void k_tprep(const float* __restrict__ ts) {
    int i = blockIdx.x * blockDim.x + threadIdx.x;
    if (i >= B_ * T_) return;
    int b = i / T_, t = i % T_;
    float t1 = ts[b * T_ + t];
    float t0 = (t == 0) ? ts[b * T_] : ts[b * T_ + t - 1];
    g_t0[i] = t0;
    g_dt[i] = (t1 - t0) * 0.25f;
}

__global__ void k_zero_h() {
    int i = blockIdx.x * blockDim.x + threadIdx.x;
    if (i < B_ * H_) g_h[i] = 0.0f;
}

__global__ void k_gate(int t) {
    int idx = blockIdx.x * blockDim.x + threadIdx.x;
    if (idx >= B_ * H_) return;
    int b = idx >> 9, j = idx & (H_ - 1);
    const float* gi = &g_gi[(size_t)(b * T_ + t) * H3_];
    const float* gh = &g_gh[(size_t)b * H3_];
    float r = 1.0f / (1.0f + expf(-(gi[j] + gh[j])));
    float z = 1.0f / (1.0f + expf(-(gi[j + H_] + gh[j + H_])));
    float n = tanhf(gi[j + 2 * H_] + r * gh[j + 2 * H_]);
    g_h[idx] = (1.0f - z) * n + z * g_h[idx];
}

__global__ void k_fin(float* __restrict__ out) {
    int i = blockIdx.x * blockDim.x + threadIdx.x;
    if (i >= B_ * H_) return;
    out[B_ * 2 * LAT_ + i] = g_h[i];          // h
    out[B_ * 2 * LAT_ + B_ * H_ + i] = 0.0f;  // c (never updated from zeros)
}

// ---------------- bf16x3 tensor-core GEMM, C[M,N] = epi(A[M,K] @ W[N,K]^T) ----------------
// MODE: 0 = +bias            (gi, gh, out)
//       1 = swish(+bias)     (layer 2)
//       2 = swish(+bias + t*w1t)   (layer 1, handles the K=513 t-column)
//       3..6 = +b3 then RK4 epilogue K1..K4 (layer 3)
__device__ __forceinline__ void mma16816(float* c, const unsigned* a, const unsigned* b) {
    asm volatile(
        "mma.sync.aligned.m16n8k16.row.col.f32.bf16.bf16.f32 "
        "{%0,%1,%2,%3}, {%4,%5,%6,%7}, {%8,%9}, {%0,%1,%2,%3};\n"
        : "+f"(c[0]), "+f"(c[1]), "+f"(c[2]), "+f"(c[3])
        : "r"(a[0]), "r"(a[1]), "r"(a[2]), "r"(a[3]), "r"(b[0]), "r"(b[1]));
}

template <int MODE>
__global__ __launch_bounds__(128) void k_gemm(
    const float* __restrict__ A, const __nv_bfloat16* __restrict__ Whi,
    const __nv_bfloat16* __restrict__ Wlo, const float* __restrict__ bias,
    float* __restrict__ C, int M, int N, int K, int tstep, float spc) {
    __shared__ alignas(16) __nv_bfloat16 sAhi[64][34];
    __shared__ alignas(16) __nv_bfloat16 sAlo[64][34];
    __shared__ alignas(16) __nv_bfloat16 sWhi[64][34];
    __shared__ alignas(16) __nv_bfloat16 sWlo[64][34];

    const int tid = threadIdx.x, lane = tid & 31, warp = tid >> 5;
    const int rowBase = blockIdx.y * 64, colBase = blockIdx.x * 64;
    const int wm = (warp >> 1) * 32, wn = (warp & 1) * 32;

    float acc[2][4][4];
#pragma unroll
    for (int mi = 0; mi < 2; mi++)
#pragma unroll
        for (int ni = 0; ni < 4; ni++)
#pragma unroll
            for (int e = 0; e < 4; e++) acc[mi][ni][e] = 0.0f;

    for (int k0 = 0; k0 < K; k0 += 32) {
        // A tile 64x32 fp32 -> split into bf16 hi/lo
#pragma unroll
        for (int i = 0; i < 16; i++) {
            int idx = i * 128 + tid;
            int r = idx >> 5, c = idx & 31;
            float v = A[(size_t)(rowBase + r) * K + k0 + c];
            __nv_bfloat16 h = __float2bfloat16(v);
            sAhi[r][c] = h;
            sAlo[r][c] = __float2bfloat16(v - __bfloat162float(h));
        }
        // W tiles 64x32 bf16 (pre-split), 32-bit loads
#pragma unroll
        for (int i = 0; i < 8; i++) {
            int idx = i * 128 + tid;
            int r = idx >> 4, c2 = idx & 15;
            const unsigned* ph = (const unsigned*)(Whi + (size_t)(colBase + r) * K + k0);
            const unsigned* pl = (const unsigned*)(Wlo + (size_t)(colBase + r) * K + k0);
            *(unsigned*)&sWhi[r][c2 * 2] = ph[c2];
            *(unsigned*)&sWlo[r][c2 * 2] = pl[c2];
        }
        __syncthreads();

#pragma unroll
        for (int kk = 0; kk < 2; kk++) {
            const int c0 = (lane & 3) * 2 + kk * 16;
            unsigned ah[2][4], al[2][4], bh[4][2], bl[4][2];
#pragma unroll
            for (int mi = 0; mi < 2; mi++) {
                int r0 = wm + mi * 16 + (lane >> 2);
                ah[mi][0] = *(const unsigned*)&sAhi[r0][c0];
                ah[mi][1] = *(const unsigned*)&sAhi[r0 + 8][c0];
                ah[mi][2] = *(const unsigned*)&sAhi[r0][c0 + 8];
                ah[mi][3] = *(const unsigned*)&sAhi[r0 + 8][c0 + 8];
                al[mi][0] = *(const unsigned*)&sAlo[r0][c0];
                al[mi][1] = *(const unsigned*)&sAlo[r0 + 8][c0];
                al[mi][2] = *(const unsigned*)&sAlo[r0][c0 + 8];
                al[mi][3] = *(const unsigned*)&sAlo[r0 + 8][c0 + 8];
            }
#pragma unroll
            for (int ni = 0; ni < 4; ni++) {
                int n0 = wn + ni * 8 + (lane >> 2);
                bh[ni][0] = *(const unsigned*)&sWhi[n0][c0];
                bh[ni][1] = *(const unsigned*)&sWhi[n0][c0 + 8];
                bl[ni][0] = *(const unsigned*)&sWlo[n0][c0];
                bl[ni][1] = *(const unsigned*)&sWlo[n0][c0 + 8];
            }
#pragma unroll
            for (int mi = 0; mi < 2; mi++)
#pragma unroll
                for (int ni = 0; ni < 4; ni++) {
                    mma16816(acc[mi][ni], ah[mi], bh[ni]);
                    mma16816(acc[mi][ni], ah[mi], bl[ni]);
                    mma16816(acc[mi][ni], al[mi], bh[ni]);
                }
        }
        __syncthreads();
    }

    // epilogue
#pragma unroll
    for (int mi = 0; mi < 2; mi++) {
        int r0 = rowBase + wm + mi * 16 + (lane >> 2);
#pragma unroll
        for (int half = 0; half < 2; half++) {
            int r = r0 + half * 8;
            float tval = 0.0f, dtv = 0.0f;
            if (MODE == 2) {
                float tt0 = g_t0[r * T_ + tstep];
                float dd = g_dt[r * T_ + tstep];
                tval = tt0 + spc * dd;
            }
            if (MODE >= 3) dtv = g_dt[r * T_ + tstep];
#pragma unroll
            for (int ni = 0; ni < 4; ni++) {
#pragma unroll
                for (int e = 0; e < 2; e++) {
                    int c = colBase + wn + ni * 8 + (lane & 3) * 2 + e;
                    float v = acc[mi][ni][half * 2 + e] + bias[c];
                    if (MODE == 0) {
                        C[(size_t)r * N + c] = v;
                    } else if (MODE == 1 || MODE == 2) {
                        if (MODE == 2) v += tval * g_w1t[c];
                        v = v / (1.0f + __expf(-v));  // swish
                        C[(size_t)r * N + c] = v;
                    } else {
                        int o = r * H_ + c;  // M=B, N=H here
                        float hv = g_h[o];
                        if (MODE == 3) { g_hin[o] = hv + 0.5f * dtv * v; g_kacc[o] = v; }
                        if (MODE == 4) { g_hin[o] = hv + 0.5f * dtv * v; g_kacc[o] += 2.0f * v; }
                        if (MODE == 5) { g_hin[o] = hv + dtv * v;        g_kacc[o] += 2.0f * v; }
                        if (MODE == 6) { g_h[o] = hv + (dtv * (1.0f / 6.0f)) * (g_kacc[o] + v); }
                    }
                }
            }
        }
    }
}

// ---------------- host launch ----------------
template <typename Tp>
static Tp* symaddr(const void* sym) {
    void* p = nullptr;
    cudaGetSymbolAddress(&p, sym);
    return (Tp*)p;
}

extern "C" void kernel_launch(void* const* d_in, const int* in_sizes, int n_in,
                              void* d_out, int out_size) {
    const float* x    = (const float*)d_in[0];
    const float* ts   = (const float*)d_in[1];
    const float* Wih  = (const float*)d_in[2];
    const float* Whh  = (const float*)d_in[3];
    const float* bih  = (const float*)d_in[4];
    const float* bhh  = (const float*)d_in[5];
    const float* Wout = (const float*)d_in[6];
    const float* bout = (const float*)d_in[7];
    const float* W1   = (const float*)d_in[8];
    const float* b1   = (const float*)d_in[9];
    const float* W2   = (const float*)d_in[10];
    const float* b2   = (const float*)d_in[11];
    const float* W3   = (const float*)d_in[12];
    const float* b3   = (const float*)d_in[13];
    float* out = (float*)d_out;

    __nv_bfloat16* pWihhi = symaddr<__nv_bfloat16>(g_Wihhi);
    __nv_bfloat16* pWihlo = symaddr<__nv_bfloat16>(g_Wihlo);
    __nv_bfloat16* pWhhhi = symaddr<__nv_bfloat16>(g_Whhhi);
    __nv_bfloat16* pWhhlo = symaddr<__nv_bfloat16>(g_Whhlo);
    __nv_bfloat16* pW1hi  = symaddr<__nv_bfloat16>(g_W1hi);
    __nv_bfloat16* pW1lo  = symaddr<__nv_bfloat16>(g_W1lo);
    __nv_bfloat16* pW2hi  = symaddr<__nv_bfloat16>(g_W2hi);
    __nv_bfloat16* pW2lo  = symaddr<__nv_bfloat16>(g_W2lo);
    __nv_bfloat16* pW3hi  = symaddr<__nv_bfloat16>(g_W3hi);
    __nv_bfloat16* pW3lo  = symaddr<__nv_bfloat16>(g_W3lo);
    __nv_bfloat16* pWohi  = symaddr<__nv_bfloat16>(g_Wouthi);
    __nv_bfloat16* pWolo  = symaddr<__nv_bfloat16>(g_Woutlo);
    float* pH   = symaddr<float>(g_h);
    float* pHin = symaddr<float>(g_hin);
    float* pA1  = symaddr<float>(g_a1);
    float* pA2  = symaddr<float>(g_a2);
    float* pGh  = symaddr<float>(g_gh);
    float* pGi  = symaddr<float>(g_gi);

    const int TPB = 256;
    // weight decomposition (idempotent, cheap)
    k_split<<<(H3_ * D_ + TPB - 1) / TPB, TPB>>>(Wih, pWihhi, pWihlo, H3_ * D_);
    k_split<<<(H3_ * H_ + TPB - 1) / TPB, TPB>>>(Whh, pWhhhi, pWhhlo, H3_ * H_);
    k_split<<<(H2_ * H2_ + TPB - 1) / TPB, TPB>>>(W2, pW2hi, pW2lo, H2_ * H2_);
    k_split<<<(H_ * H2_ + TPB - 1) / TPB, TPB>>>(W3, pW3hi, pW3lo, H_ * H2_);
    k_split<<<(2 * LAT_ * H_ + TPB - 1) / TPB, TPB>>>(Wout, pWohi, pWolo, 2 * LAT_ * H_);
    k_split_w1<<<(H2_ * H_ + TPB - 1) / TPB, TPB>>>(W1);
    k_tprep<<<(B_ * T_ + TPB - 1) / TPB, TPB>>>(ts);
    k_zero_h<<<(B_ * H_ + TPB - 1) / TPB, TPB>>>();

    // gi = x @ Wih^T + bih for all (b, t) in one GEMM: (B*T, 3H)
    k_gemm<0><<<dim3(H3_ / 64, (B_ * T_) / 64), 128>>>(x, pWihhi, pWihlo, bih, pGi,
                                                       B_ * T_, H3_, D_, 0, 0.0f);

    for (int t = 0; t < T_; t++) {
        for (int s = 0; s < 4; s++) {
            const float spc[4] = {(float)s, (float)s + 0.5f, (float)s + 0.5f, (float)s + 1.0f};
            for (int e = 0; e < 4; e++) {
                const float* Ain = (e == 0) ? pH : pHin;
                // layer 1: (B, 2H) <- swish(z @ W1^T + b1), t-column fused
                k_gemm<2><<<dim3(H2_ / 64, B_ / 64), 128>>>(Ain, pW1hi, pW1lo, b1, pA1,
                                                            B_, H2_, H_, t, spc[e]);
                // layer 2: (B, 2H) <- swish(a1 @ W2^T + b2)
                k_gemm<1><<<dim3(H2_ / 64, B_ / 64), 128>>>(pA1, pW2hi, pW2lo, b2, pA2,
                                                            B_, H2_, H2_, t, 0.0f);
                // layer 3 + fused RK4 stage epilogue
                dim3 g3(H_ / 64, B_ / 64);
                if (e == 0) k_gemm<3><<<g3, 128>>>(pA2, pW3hi, pW3lo, b3, nullptr, B_, H_, H2_, t, 0.0f);
                if (e == 1) k_gemm<4><<<g3, 128>>>(pA2, pW3hi, pW3lo, b3, nullptr, B_, H_, H2_, t, 0.0f);
                if (e == 2) k_gemm<5><<<g3, 128>>>(pA2, pW3hi, pW3lo, b3, nullptr, B_, H_, H2_, t, 0.0f);
                if (e == 3) k_gemm<6><<<g3, 128>>>(pA2, pW3hi, pW3lo, b3, nullptr, B_, H_, H2_, t, 0.0f);
            }
        }
        // GRU: gh = h @ Whh^T + bhh, then gate combine
        k_gemm<0><<<dim3(H3_ / 64, B_ / 64), 128>>>(pH, pWhhhi, pWhhlo, bhh, pGh,
                                                    B_, H3_, H_, 0, 0.0f);
        k_gate<<<(B_ * H_ + TPB - 1) / TPB, TPB>>>(t);
    }

    // out = h @ Wout^T + bout  -> d_out[0 : B*2LAT]
    k_gemm<0><<<dim3((2 * LAT_) / 64, B_ / 64), 128>>>(pH, pWohi, pWolo, bout, out,
                                                       B_, 2 * LAT_, H_, 0, 0.0f);
    // h and c regions of d_out
    k_fin<<<(B_ * H_ + TPB - 1) / TPB, TPB>>>(out);
}

// round 2
// speedup vs baseline: 1.1192x; 1.1192x over previous
#include <cuda_runtime.h>
#include <cuda_bf16.h>
#include <cstdint>

#define B_ 512
#define T_ 8
#define D_ 512
#define H_ 512
#define LAT_ 64
#define H2_ 1024
#define H3_ 1536
#define NCTA 128
#define NTHR 128

// ---------------- persistent device scratch ----------------
__device__ __align__(16) float g_h[B_ * H_];
__device__ __align__(16) float g_kacc[B_ * H_];
__device__ __align__(16) float g_gh[B_ * H3_];
__device__ __align__(16) float g_gi[B_ * T_ * H3_];
__device__ __align__(16) float g_t0[B_ * T_];
__device__ __align__(16) float g_dt[B_ * T_];
__device__ __align__(16) float g_w1t[H2_];
__device__ unsigned long long g_bar;

__device__ __align__(16) __nv_bfloat16 g_h_hi[B_ * H_], g_h_lo[B_ * H_];
__device__ __align__(16) __nv_bfloat16 g_hin_hi[B_ * H_], g_hin_lo[B_ * H_];
__device__ __align__(16) __nv_bfloat16 g_a1hi[B_ * H2_], g_a1lo[B_ * H2_];
__device__ __align__(16) __nv_bfloat16 g_a2hi[B_ * H2_], g_a2lo[B_ * H2_];
__device__ __align__(16) __nv_bfloat16 g_x_hi[B_ * T_ * D_], g_x_lo[B_ * T_ * D_];

__device__ __align__(16) __nv_bfloat16 g_W1hi[H2_ * H_], g_W1lo[H2_ * H_];
__device__ __align__(16) __nv_bfloat16 g_W2hi[H2_ * H2_], g_W2lo[H2_ * H2_];
__device__ __align__(16) __nv_bfloat16 g_W3hi[H_ * H2_], g_W3lo[H_ * H2_];
__device__ __align__(16) __nv_bfloat16 g_Wihhi[H3_ * D_], g_Wihlo[H3_ * D_];
__device__ __align__(16) __nv_bfloat16 g_Whhhi[H3_ * H_], g_Whhlo[H3_ * H_];
__device__ __align__(16) __nv_bfloat16 g_Wouthi[2 * LAT_ * H_], g_Woutlo[2 * LAT_ * H_];

// ---------------- prep kernels ----------------
__global__ void k_split(const float* __restrict__ src, __nv_bfloat16* __restrict__ hi,
                        __nv_bfloat16* __restrict__ lo, int n) {
    int i = blockIdx.x * blockDim.x + threadIdx.x;
    if (i >= n) return;
    float v = src[i];
    __nv_bfloat16 h = __float2bfloat16(v);
    hi[i] = h;
    lo[i] = __float2bfloat16(v - __bfloat162float(h));
}

__global__ void k_split_w1(const float* __restrict__ W1) {
    int i = blockIdx.x * blockDim.x + threadIdx.x;
    if (i < H2_ * H_) {
        int r = i >> 9, c = i & (H_ - 1);
        float v = W1[r * (H_ + 1) + c];
        __nv_bfloat16 h = __float2bfloat16(v);
        g_W1hi[i] = h;
        g_W1lo[i] = __float2bfloat16(v - __bfloat162float(h));
    }
    if (i < H2_) g_w1t[i] = W1[i * (H_ + 1) + H_];
}

__global__ void k_tprep(const float* __restrict__ ts) {
    int i = blockIdx.x * blockDim.x + threadIdx.x;
    if (i >= B_ * T_) return;
    int b = i / T_, t = i % T_;
    float t1 = ts[b * T_ + t];
    float t0 = (t == 0) ? ts[b * T_] : ts[b * T_ + t - 1];
    g_t0[i] = t0;
    g_dt[i] = (t1 - t0) * 0.25f;
}

__global__ void k_reset() {
    int i = blockIdx.x * blockDim.x + threadIdx.x;
    if (i == 0) g_bar = 0ull;
    if (i < B_ * H_) {
        g_h[i] = 0.0f;
        __nv_bfloat16 z = __float2bfloat16(0.0f);
        g_h_hi[i] = z;
        g_h_lo[i] = z;
    }
}

// ---------------- device helpers ----------------
__device__ __forceinline__ void cp16cg(void* s, const void* g) {
    unsigned sa = (unsigned)__cvta_generic_to_shared(s);
    asm volatile("cp.async.cg.shared.global [%0], [%1], 16;\n" ::"r"(sa), "l"(g));
}
__device__ __forceinline__ void cp16ca(void* s, const void* g) {
    unsigned sa = (unsigned)__cvta_generic_to_shared(s);
    asm volatile("cp.async.ca.shared.global [%0], [%1], 16;\n" ::"r"(sa), "l"(g));
}
__device__ __forceinline__ void mma16816(float* c, const unsigned* a, const unsigned* b) {
    asm volatile(
        "mma.sync.aligned.m16n8k16.row.col.f32.bf16.bf16.f32 "
        "{%0,%1,%2,%3}, {%4,%5,%6,%7}, {%8,%9}, {%0,%1,%2,%3};\n"
        : "+f"(c[0]), "+f"(c[1]), "+f"(c[2]), "+f"(c[3])
        : "r"(a[0]), "r"(a[1]), "r"(a[2]), "r"(a[3]), "r"(b[0]), "r"(b[1]));
}
__device__ __forceinline__ void split_store2(__nv_bfloat16* Hi, __nv_bfloat16* Lo, int o,
                                             float v0, float v1) {
    __nv_bfloat16 h0 = __float2bfloat16(v0), h1 = __float2bfloat16(v1);
    *(__nv_bfloat162*)&Hi[o] = __halves2bfloat162(h0, h1);
    __nv_bfloat16 l0 = __float2bfloat16(v0 - __bfloat162float(h0));
    __nv_bfloat16 l1 = __float2bfloat16(v1 - __bfloat162float(h1));
    *(__nv_bfloat162*)&Lo[o] = __halves2bfloat162(l0, l1);
}

__device__ __forceinline__ void gbar(unsigned long long& target) {
    __syncthreads();
    if (threadIdx.x == 0) {
        target += NCTA;
        __threadfence();
        atomicAdd(&g_bar, 1ull);
        unsigned long long v;
        do {
            asm volatile("ld.acquire.gpu.global.u64 %0, [%1];" : "=l"(v) : "l"(&g_bar));
            if (v < target) __nanosleep(32);
        } while (v < target);
    }
    __syncthreads();
}

// ---------------- GEMM phase: C[M,N] = epi(A @ W^T), A,W bf16 hi/lo pairs -----------
// mode 0: +bias -> fp32 C
// mode 1: swish(+bias) -> hi/lo out
// mode 2: swish(+bias + t*w1t) -> hi/lo out
// mode 3..6: +b3 then RK4 stage epilogue (writes g_h/g_hin/g_kacc + splits)
template <int TN>
__device__ __noinline__ void gemm_phase(
    const __nv_bfloat16* __restrict__ Ahi, const __nv_bfloat16* __restrict__ Alo,
    const __nv_bfloat16* __restrict__ Whi, const __nv_bfloat16* __restrict__ Wlo,
    const float* __restrict__ bias, float* Cf, __nv_bfloat16* Ohi, __nv_bfloat16* Olo,
    int M, int N, int K, int mode, int tstep, float spc, __nv_bfloat16 (*sm)[4][64][40]) {
    const int tid = threadIdx.x, lane = tid & 31, warp = tid >> 5;
    constexpr int NI = (TN == 64) ? 4 : 2;
    const int ncols = N / TN;
    const int ntiles = (M / 64) * ncols;
    const int nk = K / 32;

    for (int tile = blockIdx.x; tile < ntiles; tile += NCTA) {
        const int rowBase = (tile / ncols) * 64;
        const int colBase = (tile % ncols) * TN;
        const int wm = (warp >> 1) * 32;
        const int wn = (warp & 1) * (TN / 2);

        float acc[2][NI][4];
#pragma unroll
        for (int mi = 0; mi < 2; mi++)
#pragma unroll
            for (int ni = 0; ni < NI; ni++)
#pragma unroll
                for (int e = 0; e < 4; e++) acc[mi][ni][e] = 0.0f;

        auto fill = [&](int st, int k0) {
#pragma unroll
            for (int it = 0; it < 2; ++it) {
                int idx = it * NTHR + tid;
                int r = idx & 63, ch = idx >> 6;
                cp16cg(&sm[st][0][r][ch * 8], Ahi + (size_t)(rowBase + r) * K + k0 + ch * 8);
                cp16cg(&sm[st][1][r][ch * 8], Alo + (size_t)(rowBase + r) * K + k0 + ch * 8);
            }
#pragma unroll
            for (int it = 0; it < TN / 32; ++it) {
                int idx = it * NTHR + tid;
                int r = idx & (TN - 1), ch = idx >> ((TN == 64) ? 6 : 5);
                cp16ca(&sm[st][2][r][ch * 8], Whi + (size_t)(colBase + r) * K + k0 + ch * 8);
                cp16ca(&sm[st][3][r][ch * 8], Wlo + (size_t)(colBase + r) * K + k0 + ch * 8);
            }
            asm volatile("cp.async.commit_group;\n" ::);
        };

        fill(0, 0);
        for (int kt = 0; kt < nk; ++kt) {
            const int st = kt & 1;
            if (kt + 1 < nk) {
                fill(st ^ 1, (kt + 1) * 32);
                asm volatile("cp.async.wait_group 1;\n" ::);
            } else {
                asm volatile("cp.async.wait_group 0;\n" ::);
            }
            __syncthreads();
#pragma unroll
            for (int kk = 0; kk < 2; kk++) {
                const int c0 = (lane & 3) * 2 + kk * 16;
                unsigned ah[2][4], al[2][4], bh[NI][2], bl[NI][2];
#pragma unroll
                for (int mi = 0; mi < 2; mi++) {
                    int r0 = wm + mi * 16 + (lane >> 2);
                    ah[mi][0] = *(const unsigned*)&sm[st][0][r0][c0];
                    ah[mi][1] = *(const unsigned*)&sm[st][0][r0 + 8][c0];
                    ah[mi][2] = *(const unsigned*)&sm[st][0][r0][c0 + 8];
                    ah[mi][3] = *(const unsigned*)&sm[st][0][r0 + 8][c0 + 8];
                    al[mi][0] = *(const unsigned*)&sm[st][1][r0][c0];
                    al[mi][1] = *(const unsigned*)&sm[st][1][r0 + 8][c0];
                    al[mi][2] = *(const unsigned*)&sm[st][1][r0][c0 + 8];
                    al[mi][3] = *(const unsigned*)&sm[st][1][r0 + 8][c0 + 8];
                }
#pragma unroll
                for (int ni = 0; ni < NI; ni++) {
                    int n0 = wn + ni * 8 + (lane >> 2);
                    bh[ni][0] = *(const unsigned*)&sm[st][2][n0][c0];
                    bh[ni][1] = *(const unsigned*)&sm[st][2][n0][c0 + 8];
                    bl[ni][0] = *(const unsigned*)&sm[st][3][n0][c0];
                    bl[ni][1] = *(const unsigned*)&sm[st][3][n0][c0 + 8];
                }
#pragma unroll
                for (int mi = 0; mi < 2; mi++)
#pragma unroll
                    for (int ni = 0; ni < NI; ni++) {
                        mma16816(acc[mi][ni], ah[mi], bh[ni]);
                        mma16816(acc[mi][ni], ah[mi], bl[ni]);
                        mma16816(acc[mi][ni], al[mi], bh[ni]);
                    }
            }
            __syncthreads();
        }

        // epilogue
#pragma unroll
        for (int mi = 0; mi < 2; mi++) {
#pragma unroll
            for (int half = 0; half < 2; half++) {
                int rr = rowBase + wm + mi * 16 + (lane >> 2) + half * 8;
                float tval = 0.0f, dtv = 0.0f;
                if (mode == 2) tval = g_t0[rr * T_ + tstep] + spc * g_dt[rr * T_ + tstep];
                if (mode >= 3) dtv = g_dt[rr * T_ + tstep];
#pragma unroll
                for (int ni = 0; ni < NI; ni++) {
                    int c = colBase + wn + ni * 8 + (lane & 3) * 2;
                    float v0 = acc[mi][ni][half * 2 + 0] + bias[c];
                    float v1 = acc[mi][ni][half * 2 + 1] + bias[c + 1];
                    if (mode == 0) {
                        float2 o2 = make_float2(v0, v1);
                        *(float2*)&Cf[(size_t)rr * N + c] = o2;
                    } else if (mode <= 2) {
                        if (mode == 2) {
                            v0 += tval * g_w1t[c];
                            v1 += tval * g_w1t[c + 1];
                        }
                        v0 = v0 / (1.0f + __expf(-v0));
                        v1 = v1 / (1.0f + __expf(-v1));
                        split_store2(Ohi, Olo, rr * N + c, v0, v1);
                    } else {
                        int o = rr * H_ + c;
                        float h0 = __ldcg(&g_h[o]), h1 = __ldcg(&g_h[o + 1]);
                        if (mode == 3) {
                            g_kacc[o] = v0;
                            g_kacc[o + 1] = v1;
                            split_store2(g_hin_hi, g_hin_lo, o, h0 + 0.5f * dtv * v0,
                                         h1 + 0.5f * dtv * v1);
                        } else if (mode == 4) {
                            g_kacc[o] = __ldcg(&g_kacc[o]) + 2.0f * v0;
                            g_kacc[o + 1] = __ldcg(&g_kacc[o + 1]) + 2.0f * v1;
                            split_store2(g_hin_hi, g_hin_lo, o, h0 + 0.5f * dtv * v0,
                                         h1 + 0.5f * dtv * v1);
                        } else if (mode == 5) {
                            g_kacc[o] = __ldcg(&g_kacc[o]) + 2.0f * v0;
                            g_kacc[o + 1] = __ldcg(&g_kacc[o + 1]) + 2.0f * v1;
                            split_store2(g_hin_hi, g_hin_lo, o, h0 + dtv * v0, h1 + dtv * v1);
                        } else {
                            float n0 = h0 + (dtv * (1.0f / 6.0f)) * (__ldcg(&g_kacc[o]) + v0);
                            float n1 = h1 + (dtv * (1.0f / 6.0f)) * (__ldcg(&g_kacc[o + 1]) + v1);
                            g_h[o] = n0;
                            g_h[o + 1] = n1;
                            split_store2(g_h_hi, g_h_lo, o, n0, n1);
                        }
                    }
                }
            }
        }
    }
}

__device__ void gate_phase(int t) {
    for (int i = blockIdx.x * NTHR + threadIdx.x; i < B_ * H_; i += NCTA * NTHR) {
        int b = i >> 9, j = i & (H_ - 1);
        const float* gi = g_gi + (size_t)(b * T_ + t) * H3_;
        const float* gh = g_gh + (size_t)b * H3_;
        float ir = __ldcg(&gi[j]), iz = __ldcg(&gi[j + H_]), in = __ldcg(&gi[j + 2 * H_]);
        float hr = __ldcg(&gh[j]), hz = __ldcg(&gh[j + H_]), hn = __ldcg(&gh[j + 2 * H_]);
        float r = 1.0f / (1.0f + expf(-(ir + hr)));
        float z = 1.0f / (1.0f + expf(-(iz + hz)));
        float n = tanhf(in + r * hn);
        float h = (1.0f - z) * n + z * __ldcg(&g_h[i]);
        g_h[i] = h;
        __nv_bfloat16 hh = __float2bfloat16(h);
        g_h_hi[i] = hh;
        g_h_lo[i] = __float2bfloat16(h - __bfloat162float(hh));
    }
}

__global__ void __launch_bounds__(NTHR, 1) k_persist(
    const float* __restrict__ bih, const float* __restrict__ bhh, const float* __restrict__ b1,
    const float* __restrict__ b2, const float* __restrict__ b3, const float* __restrict__ bout,
    float* __restrict__ out) {
    __shared__ __align__(16) __nv_bfloat16 sm[2][4][64][40];
    unsigned long long bt = 0;

    // gi = x @ Wih^T + bih for all (b,t)
    gemm_phase<64>(g_x_hi, g_x_lo, g_Wihhi, g_Wihlo, bih, g_gi, nullptr, nullptr, B_ * T_, H3_,
                   D_, 0, 0, 0.0f, sm);
    gbar(bt);

#pragma unroll 1
    for (int t = 0; t < T_; t++) {
#pragma unroll 1
        for (int s = 0; s < 4; s++) {
#pragma unroll 1
            for (int e = 0; e < 4; e++) {
                float spc = (float)s + ((e == 1 || e == 2) ? 0.5f : (e == 3 ? 1.0f : 0.0f));
                const __nv_bfloat16* Ah = e ? g_hin_hi : g_h_hi;
                const __nv_bfloat16* Al = e ? g_hin_lo : g_h_lo;
                gemm_phase<64>(Ah, Al, g_W1hi, g_W1lo, b1, nullptr, g_a1hi, g_a1lo, B_, H2_, H_,
                               2, t, spc, sm);
                gbar(bt);
                gemm_phase<64>(g_a1hi, g_a1lo, g_W2hi, g_W2lo, b2, nullptr, g_a2hi, g_a2lo, B_,
                               H2_, H2_, 1, t, 0.0f, sm);
                gbar(bt);
                gemm_phase<32>(g_a2hi, g_a2lo, g_W3hi, g_W3lo, b3, nullptr, nullptr, nullptr, B_,
                               H_, H2_, 3 + e, t, 0.0f, sm);
                gbar(bt);
            }
        }
        gemm_phase<32>(g_h_hi, g_h_lo, g_Whhhi, g_Whhlo, bhh, g_gh, nullptr, nullptr, B_, H3_,
                       H_, 0, 0, 0.0f, sm);
        gbar(bt);
        gate_phase(t);
        gbar(bt);
    }

    // out = h @ Wout^T + bout
    gemm_phase<32>(g_h_hi, g_h_lo, g_Wouthi, g_Woutlo, bout, out, nullptr, nullptr, B_,
                   2 * LAT_, H_, 0, 0, 0.0f, sm);
    // h and c tail regions
    for (int i = blockIdx.x * NTHR + threadIdx.x; i < B_ * H_; i += NCTA * NTHR) {
        out[B_ * 2 * LAT_ + i] = __ldcg(&g_h[i]);
        out[B_ * 2 * LAT_ + B_ * H_ + i] = 0.0f;
    }
}

// ---------------- host ----------------
template <typename Tp>
static Tp* symaddr(const void* sym) {
    void* p = nullptr;
    cudaGetSymbolAddress(&p, sym);
    return (Tp*)p;
}

extern "C" void kernel_launch(void* const* d_in, const int* in_sizes, int n_in,
                              void* d_out, int out_size) {
    const float* x    = (const float*)d_in[0];
    const float* ts   = (const float*)d_in[1];
    const float* Wih  = (const float*)d_in[2];
    const float* Whh  = (const float*)d_in[3];
    const float* bih  = (const float*)d_in[4];
    const float* bhh  = (const float*)d_in[5];
    const float* Wout = (const float*)d_in[6];
    const float* bout = (const float*)d_in[7];
    const float* W1   = (const float*)d_in[8];
    const float* b1   = (const float*)d_in[9];
    const float* W2   = (const float*)d_in[10];
    const float* b2   = (const float*)d_in[11];
    const float* W3   = (const float*)d_in[12];
    const float* b3   = (const float*)d_in[13];
    float* out = (float*)d_out;

    const int TPB = 256;
    k_split<<<(H3_ * D_ + TPB - 1) / TPB, TPB>>>(Wih, symaddr<__nv_bfloat16>(g_Wihhi),
                                                 symaddr<__nv_bfloat16>(g_Wihlo), H3_ * D_);
    k_split<<<(H3_ * H_ + TPB - 1) / TPB, TPB>>>(Whh, symaddr<__nv_bfloat16>(g_Whhhi),
                                                 symaddr<__nv_bfloat16>(g_Whhlo), H3_ * H_);
    k_split<<<(H2_ * H2_ + TPB - 1) / TPB, TPB>>>(W2, symaddr<__nv_bfloat16>(g_W2hi),
                                                  symaddr<__nv_bfloat16>(g_W2lo), H2_ * H2_);
    k_split<<<(H_ * H2_ + TPB - 1) / TPB, TPB>>>(W3, symaddr<__nv_bfloat16>(g_W3hi),
                                                 symaddr<__nv_bfloat16>(g_W3lo), H_ * H2_);
    k_split<<<(2 * LAT_ * H_ + TPB - 1) / TPB, TPB>>>(Wout, symaddr<__nv_bfloat16>(g_Wouthi),
                                                      symaddr<__nv_bfloat16>(g_Woutlo),
                                                      2 * LAT_ * H_);
    k_split<<<(B_ * T_ * D_ + TPB - 1) / TPB, TPB>>>(x, symaddr<__nv_bfloat16>(g_x_hi),
                                                     symaddr<__nv_bfloat16>(g_x_lo),
                                                     B_ * T_ * D_);
    k_split_w1<<<(H2_ * H_ + TPB - 1) / TPB, TPB>>>(W1);
    k_tprep<<<(B_ * T_ + TPB - 1) / TPB, TPB>>>(ts);
    k_reset<<<(B_ * H_ + TPB - 1) / TPB, TPB>>>();

    k_persist<<<NCTA, NTHR>>>(bih, bhh, b1, b2, b3, bout, out);
}

// round 6
// speedup vs baseline: 1.6770x; 1.4985x over previous
#include <cuda_runtime.h>
#include <cuda_bf16.h>
#include <cstdint>

#define B_ 512
#define T_ 8
#define D_ 512
#define H_ 512
#define LAT_ 64
#define H2_ 1024
#define H3_ 1536
#define NCTA 128
#define NTHR 256

// ---------------- persistent device scratch ----------------
__device__ __align__(16) float g_h[B_ * H_];
__device__ __align__(16) float g_kacc[B_ * H_];
__device__ __align__(16) float g_gh[B_ * H3_];
__device__ __align__(16) float g_gi[B_ * T_ * H3_];
__device__ __align__(16) float g_t0[B_ * T_];
__device__ __align__(16) float g_dt[B_ * T_];
__device__ __align__(16) float g_w1t[H2_];
__device__ unsigned long long g_bar;

__device__ __align__(16) __nv_bfloat16 g_h_hi[B_ * H_], g_h_lo[B_ * H_];
__device__ __align__(16) __nv_bfloat16 g_hin_hi[B_ * H_], g_hin_lo[B_ * H_];
__device__ __align__(16) __nv_bfloat16 g_a1hi[B_ * H2_], g_a1lo[B_ * H2_];
__device__ __align__(16) __nv_bfloat16 g_a2hi[B_ * H2_], g_a2lo[B_ * H2_];
__device__ __align__(16) __nv_bfloat16 g_x_hi[B_ * T_ * D_], g_x_lo[B_ * T_ * D_];

__device__ __align__(16) __nv_bfloat16 g_W1hi[H2_ * H_], g_W1lo[H2_ * H_];
__device__ __align__(16) __nv_bfloat16 g_W2hi[H2_ * H2_], g_W2lo[H2_ * H2_];
__device__ __align__(16) __nv_bfloat16 g_W3hi[H_ * H2_], g_W3lo[H_ * H2_];
__device__ __align__(16) __nv_bfloat16 g_Wihhi[H3_ * D_], g_Wihlo[H3_ * D_];
__device__ __align__(16) __nv_bfloat16 g_Whhhi[H3_ * H_], g_Whhlo[H3_ * H_];
__device__ __align__(16) __nv_bfloat16 g_Wouthi[2 * LAT_ * H_], g_Woutlo[2 * LAT_ * H_];

// ---------------- prep kernels ----------------
__global__ void k_split(const float* __restrict__ src, __nv_bfloat16* __restrict__ hi,
                        __nv_bfloat16* __restrict__ lo, int n) {
    int i = blockIdx.x * blockDim.x + threadIdx.x;
    if (i >= n) return;
    float v = src[i];
    __nv_bfloat16 h = __float2bfloat16(v);
    hi[i] = h;
    lo[i] = __float2bfloat16(v - __bfloat162float(h));
}

__global__ void k_split_w1(const float* __restrict__ W1) {
    int i = blockIdx.x * blockDim.x + threadIdx.x;
    if (i < H2_ * H_) {
        int r = i >> 9, c = i & (H_ - 1);
        float v = W1[r * (H_ + 1) + c];
        __nv_bfloat16 h = __float2bfloat16(v);
        g_W1hi[i] = h;
        g_W1lo[i] = __float2bfloat16(v - __bfloat162float(h));
    }
    if (i < H2_) g_w1t[i] = W1[i * (H_ + 1) + H_];
}

__global__ void k_tprep(const float* __restrict__ ts) {
    int i = blockIdx.x * blockDim.x + threadIdx.x;
    if (i >= B_ * T_) return;
    int b = i / T_, t = i % T_;
    float t1 = ts[b * T_ + t];
    float t0 = (t == 0) ? ts[b * T_] : ts[b * T_ + t - 1];
    g_t0[i] = t0;
    g_dt[i] = (t1 - t0) * 0.25f;
}

__global__ void k_reset() {
    int i = blockIdx.x * blockDim.x + threadIdx.x;
    if (i == 0) g_bar = 0ull;
    if (i < B_ * H_) {
        g_h[i] = 0.0f;
        __nv_bfloat16 z = __float2bfloat16(0.0f);
        g_h_hi[i] = z;
        g_h_lo[i] = z;
    }
}

// ---------------- device helpers ----------------
__device__ __forceinline__ void cp16cg(void* s, const void* g) {
    unsigned sa = (unsigned)__cvta_generic_to_shared(s);
    asm volatile("cp.async.cg.shared.global [%0], [%1], 16;\n" ::"r"(sa), "l"(g));
}
__device__ __forceinline__ void cp16ca(void* s, const void* g) {
    unsigned sa = (unsigned)__cvta_generic_to_shared(s);
    asm volatile("cp.async.ca.shared.global [%0], [%1], 16;\n" ::"r"(sa), "l"(g));
}
__device__ __forceinline__ void mma16816(float* c, const unsigned* a, const unsigned* b) {
    asm volatile(
        "mma.sync.aligned.m16n8k16.row.col.f32.bf16.bf16.f32 "
        "{%0,%1,%2,%3}, {%4,%5,%6,%7}, {%8,%9}, {%0,%1,%2,%3};\n"
        : "+f"(c[0]), "+f"(c[1]), "+f"(c[2]), "+f"(c[3])
        : "r"(a[0]), "r"(a[1]), "r"(a[2]), "r"(a[3]), "r"(b[0]), "r"(b[1]));
}
__device__ __forceinline__ void split_store2(__nv_bfloat16* Hi, __nv_bfloat16* Lo, int o,
                                             float v0, float v1) {
    __nv_bfloat16 h0 = __float2bfloat16(v0), h1 = __float2bfloat16(v1);
    *(__nv_bfloat162*)&Hi[o] = __halves2bfloat162(h0, h1);
    __nv_bfloat16 l0 = __float2bfloat16(v0 - __bfloat162float(h0));
    __nv_bfloat16 l1 = __float2bfloat16(v1 - __bfloat162float(h1));
    *(__nv_bfloat162*)&Lo[o] = __halves2bfloat162(l0, l1);
}

__device__ __forceinline__ void gbar(unsigned long long& target) {
    __syncthreads();
    if (threadIdx.x == 0) {
        target += NCTA;
        __threadfence();
        atomicAdd(&g_bar, 1ull);
        unsigned long long v;
        do {
            asm volatile("ld.acquire.gpu.global.u64 %0, [%1];" : "=l"(v) : "l"(&g_bar));
            if (v < target) __nanosleep(32);
        } while (v < target);
    }
    __syncthreads();
}

// ---------------- GEMM phase: C[M,N] = epi(A @ W^T), A,W bf16 hi/lo pairs -----------
// 8 warps: warp row = warp>>2 (2x32 rows), warp col = warp&3 (4 x TN/4 cols)
// mode 0: +bias -> fp32 C
// mode 1: swish(+bias) -> hi/lo out
// mode 2: swish(+bias + t*w1t) -> hi/lo out
// mode 3..6: +b3 then RK4 stage epilogue
template <int TN>
__device__ __noinline__ void gemm_phase(
    const __nv_bfloat16* __restrict__ Ahi, const __nv_bfloat16* __restrict__ Alo,
    const __nv_bfloat16* __restrict__ Whi, const __nv_bfloat16* __restrict__ Wlo,
    const float* __restrict__ bias, float* Cf, __nv_bfloat16* Ohi, __nv_bfloat16* Olo,
    int M, int N, int K, int mode, int tstep, float spc, __nv_bfloat16 (*sm)[4][64][40]) {
    const int tid = threadIdx.x, lane = tid & 31, warp = tid >> 5;
    constexpr int NI = TN / 32;  // n8 tiles per warp (64 -> 2, 32 -> 1)
    const int ncols = N / TN;
    const int ntiles = (M / 64) * ncols;
    const int nk = K / 32;

    const int wm = (warp >> 2) * 32;
    const int wn = (warp & 3) * (TN / 4);

    for (int tile = blockIdx.x; tile < ntiles; tile += NCTA) {
        const int rowBase = (tile / ncols) * 64;
        const int colBase = (tile % ncols) * TN;

        float acc[2][NI][4];
#pragma unroll
        for (int mi = 0; mi < 2; mi++)
#pragma unroll
            for (int ni = 0; ni < NI; ni++)
#pragma unroll
                for (int e = 0; e < 4; e++) acc[mi][ni][e] = 0.0f;

        auto fill = [&](int st, int k0) {
            // A tiles: 64 rows x 32 bf16 = 4 x 16B chunks per row -> 256 cp per tile
            int r = tid >> 2, ch = tid & 3;
            cp16cg(&sm[st][0][r][ch * 8], Ahi + (size_t)(rowBase + r) * K + k0 + ch * 8);
            cp16cg(&sm[st][1][r][ch * 8], Alo + (size_t)(rowBase + r) * K + k0 + ch * 8);
            // W tiles: TN rows x 32 bf16
            if (TN == 64) {
                cp16ca(&sm[st][2][r][ch * 8], Whi + (size_t)(colBase + r) * K + k0 + ch * 8);
                cp16ca(&sm[st][3][r][ch * 8], Wlo + (size_t)(colBase + r) * K + k0 + ch * 8);
            } else if (tid < 128) {
                cp16ca(&sm[st][2][r][ch * 8], Whi + (size_t)(colBase + r) * K + k0 + ch * 8);
                cp16ca(&sm[st][3][r][ch * 8], Wlo + (size_t)(colBase + r) * K + k0 + ch * 8);
            }
            asm volatile("cp.async.commit_group;\n" ::);
        };

        fill(0, 0);
        for (int kt = 0; kt < nk; ++kt) {
            const int st = kt & 1;
            if (kt + 1 < nk) {
                fill(st ^ 1, (kt + 1) * 32);
                asm volatile("cp.async.wait_group 1;\n" ::);
            } else {
                asm volatile("cp.async.wait_group 0;\n" ::);
            }
            __syncthreads();
#pragma unroll
            for (int kk = 0; kk < 2; kk++) {
                const int c0 = (lane & 3) * 2 + kk * 16;
                unsigned ah[2][4], al[2][4], bh[NI][2], bl[NI][2];
#pragma unroll
                for (int mi = 0; mi < 2; mi++) {
                    int r0 = wm + mi * 16 + (lane >> 2);
                    ah[mi][0] = *(const unsigned*)&sm[st][0][r0][c0];
                    ah[mi][1] = *(const unsigned*)&sm[st][0][r0 + 8][c0];
                    ah[mi][2] = *(const unsigned*)&sm[st][0][r0][c0 + 8];
                    ah[mi][3] = *(const unsigned*)&sm[st][0][r0 + 8][c0 + 8];
                    al[mi][0] = *(const unsigned*)&sm[st][1][r0][c0];
                    al[mi][1] = *(const unsigned*)&sm[st][1][r0 + 8][c0];
                    al[mi][2] = *(const unsigned*)&sm[st][1][r0][c0 + 8];
                    al[mi][3] = *(const unsigned*)&sm[st][1][r0 + 8][c0 + 8];
                }
#pragma unroll
                for (int ni = 0; ni < NI; ni++) {
                    int n0 = wn + ni * 8 + (lane >> 2);
                    bh[ni][0] = *(const unsigned*)&sm[st][2][n0][c0];
                    bh[ni][1] = *(const unsigned*)&sm[st][2][n0][c0 + 8];
                    bl[ni][0] = *(const unsigned*)&sm[st][3][n0][c0];
                    bl[ni][1] = *(const unsigned*)&sm[st][3][n0][c0 + 8];
                }
#pragma unroll
                for (int mi = 0; mi < 2; mi++)
#pragma unroll
                    for (int ni = 0; ni < NI; ni++) {
                        mma16816(acc[mi][ni], ah[mi], bh[ni]);
                        mma16816(acc[mi][ni], ah[mi], bl[ni]);
                        mma16816(acc[mi][ni], al[mi], bh[ni]);
                    }
            }
            __syncthreads();
        }

        // epilogue
#pragma unroll
        for (int mi = 0; mi < 2; mi++) {
#pragma unroll
            for (int half = 0; half < 2; half++) {
                int rr = rowBase + wm + mi * 16 + (lane >> 2) + half * 8;
                float tval = 0.0f, dtv = 0.0f;
                if (mode == 2) tval = g_t0[rr * T_ + tstep] + spc * g_dt[rr * T_ + tstep];
                if (mode >= 3) dtv = g_dt[rr * T_ + tstep];
#pragma unroll
                for (int ni = 0; ni < NI; ni++) {
                    int c = colBase + wn + ni * 8 + (lane & 3) * 2;
                    float v0 = acc[mi][ni][half * 2 + 0] + bias[c];
                    float v1 = acc[mi][ni][half * 2 + 1] + bias[c + 1];
                    if (mode == 0) {
                        float2 o2 = make_float2(v0, v1);
                        *(float2*)&Cf[(size_t)rr * N + c] = o2;
                    } else if (mode <= 2) {
                        if (mode == 2) {
                            v0 += tval * g_w1t[c];
                            v1 += tval * g_w1t[c + 1];
                        }
                        v0 = v0 / (1.0f + __expf(-v0));
                        v1 = v1 / (1.0f + __expf(-v1));
                        split_store2(Ohi, Olo, rr * N + c, v0, v1);
                    } else {
                        int o = rr * H_ + c;
                        float h0 = __ldcg(&g_h[o]), h1 = __ldcg(&g_h[o + 1]);
                        if (mode == 3) {
                            g_kacc[o] = v0;
                            g_kacc[o + 1] = v1;
                            split_store2(g_hin_hi, g_hin_lo, o, h0 + 0.5f * dtv * v0,
                                         h1 + 0.5f * dtv * v1);
                        } else if (mode == 4) {
                            g_kacc[o] = __ldcg(&g_kacc[o]) + 2.0f * v0;
                            g_kacc[o + 1] = __ldcg(&g_kacc[o + 1]) + 2.0f * v1;
                            split_store2(g_hin_hi, g_hin_lo, o, h0 + 0.5f * dtv * v0,
                                         h1 + 0.5f * dtv * v1);
                        } else if (mode == 5) {
                            g_kacc[o] = __ldcg(&g_kacc[o]) + 2.0f * v0;
                            g_kacc[o + 1] = __ldcg(&g_kacc[o + 1]) + 2.0f * v1;
                            split_store2(g_hin_hi, g_hin_lo, o, h0 + dtv * v0, h1 + dtv * v1);
                        } else {
                            float n0 = h0 + (dtv * (1.0f / 6.0f)) * (__ldcg(&g_kacc[o]) + v0);
                            float n1 = h1 + (dtv * (1.0f / 6.0f)) * (__ldcg(&g_kacc[o + 1]) + v1);
                            g_h[o] = n0;
                            g_h[o + 1] = n1;
                            split_store2(g_h_hi, g_h_lo, o, n0, n1);
                        }
                    }
                }
            }
        }
    }
}

__device__ void gate_phase(int t) {
    for (int i = blockIdx.x * NTHR + threadIdx.x; i < B_ * H_; i += NCTA * NTHR) {
        int b = i >> 9, j = i & (H_ - 1);
        const float* gi = g_gi + (size_t)(b * T_ + t) * H3_;
        const float* gh = g_gh + (size_t)b * H3_;
        float ir = __ldcg(&gi[j]), iz = __ldcg(&gi[j + H_]), in = __ldcg(&gi[j + 2 * H_]);
        float hr = __ldcg(&gh[j]), hz = __ldcg(&gh[j + H_]), hn = __ldcg(&gh[j + 2 * H_]);
        float r = 1.0f / (1.0f + expf(-(ir + hr)));
        float z = 1.0f / (1.0f + expf(-(iz + hz)));
        float n = tanhf(in + r * hn);
        float h = (1.0f - z) * n + z * __ldcg(&g_h[i]);
        g_h[i] = h;
        __nv_bfloat16 hh = __float2bfloat16(h);
        g_h_hi[i] = hh;
        g_h_lo[i] = __float2bfloat16(h - __bfloat162float(hh));
    }
}

__global__ void __launch_bounds__(NTHR, 1) k_persist(
    const float* __restrict__ bih, const float* __restrict__ bhh, const float* __restrict__ b1,
    const float* __restrict__ b2, const float* __restrict__ b3, const float* __restrict__ bout,
    float* __restrict__ out) {
    __shared__ __align__(16) __nv_bfloat16 sm[2][4][64][40];
    unsigned long long bt = 0;

    // gi = x @ Wih^T + bih for all (b,t)
    gemm_phase<64>(g_x_hi, g_x_lo, g_Wihhi, g_Wihlo, bih, g_gi, nullptr, nullptr, B_ * T_, H3_,
                   D_, 0, 0, 0.0f, sm);
    gbar(bt);

#pragma unroll 1
    for (int t = 0; t < T_; t++) {
#pragma unroll 1
        for (int s = 0; s < 4; s++) {
#pragma unroll 1
            for (int e = 0; e < 4; e++) {
                float spc = (float)s + ((e == 1 || e == 2) ? 0.5f : (e == 3 ? 1.0f : 0.0f));
                const __nv_bfloat16* Ah = e ? g_hin_hi : g_h_hi;
                const __nv_bfloat16* Al = e ? g_hin_lo : g_h_lo;
                gemm_phase<64>(Ah, Al, g_W1hi, g_W1lo, b1, nullptr, g_a1hi, g_a1lo, B_, H2_, H_,
                               2, t, spc, sm);
                gbar(bt);
                gemm_phase<64>(g_a1hi, g_a1lo, g_W2hi, g_W2lo, b2, nullptr, g_a2hi, g_a2lo, B_,
                               H2_, H2_, 1, t, 0.0f, sm);
                gbar(bt);
                gemm_phase<32>(g_a2hi, g_a2lo, g_W3hi, g_W3lo, b3, nullptr, nullptr, nullptr, B_,
                               H_, H2_, 3 + e, t, 0.0f, sm);
                gbar(bt);
            }
        }
        gemm_phase<32>(g_h_hi, g_h_lo, g_Whhhi, g_Whhlo, bhh, g_gh, nullptr, nullptr, B_, H3_,
                       H_, 0, 0, 0.0f, sm);
        gbar(bt);
        gate_phase(t);
        gbar(bt);
    }

    // out = h @ Wout^T + bout
    gemm_phase<32>(g_h_hi, g_h_lo, g_Wouthi, g_Woutlo, bout, out, nullptr, nullptr, B_,
                   2 * LAT_, H_, 0, 0, 0.0f, sm);
    // h and c tail regions
    for (int i = blockIdx.x * NTHR + threadIdx.x; i < B_ * H_; i += NCTA * NTHR) {
        out[B_ * 2 * LAT_ + i] = __ldcg(&g_h[i]);
        out[B_ * 2 * LAT_ + B_ * H_ + i] = 0.0f;
    }
}

// ---------------- host ----------------
template <typename Tp>
static Tp* symaddr(const void* sym) {
    void* p = nullptr;
    cudaGetSymbolAddress(&p, sym);
    return (Tp*)p;
}

extern "C" void kernel_launch(void* const* d_in, const int* in_sizes, int n_in,
                              void* d_out, int out_size) {
    const float* x    = (const float*)d_in[0];
    const float* ts   = (const float*)d_in[1];
    const float* Wih  = (const float*)d_in[2];
    const float* Whh  = (const float*)d_in[3];
    const float* bih  = (const float*)d_in[4];
    const float* bhh  = (const float*)d_in[5];
    const float* Wout = (const float*)d_in[6];
    const float* bout = (const float*)d_in[7];
    const float* W1   = (const float*)d_in[8];
    const float* b1   = (const float*)d_in[9];
    const float* W2   = (const float*)d_in[10];
    const float* b2   = (const float*)d_in[11];
    const float* W3   = (const float*)d_in[12];
    const float* b3   = (const float*)d_in[13];
    float* out = (float*)d_out;

    const int TPB = 256;
    k_split<<<(H3_ * D_ + TPB - 1) / TPB, TPB>>>(Wih, symaddr<__nv_bfloat16>(g_Wihhi),
                                                 symaddr<__nv_bfloat16>(g_Wihlo), H3_ * D_);
    k_split<<<(H3_ * H_ + TPB - 1) / TPB, TPB>>>(Whh, symaddr<__nv_bfloat16>(g_Whhhi),
                                                 symaddr<__nv_bfloat16>(g_Whhlo), H3_ * H_);
    k_split<<<(H2_ * H2_ + TPB - 1) / TPB, TPB>>>(W2, symaddr<__nv_bfloat16>(g_W2hi),
                                                  symaddr<__nv_bfloat16>(g_W2lo), H2_ * H2_);
    k_split<<<(H_ * H2_ + TPB - 1) / TPB, TPB>>>(W3, symaddr<__nv_bfloat16>(g_W3hi),
                                                 symaddr<__nv_bfloat16>(g_W3lo), H_ * H2_);
    k_split<<<(2 * LAT_ * H_ + TPB - 1) / TPB, TPB>>>(Wout, symaddr<__nv_bfloat16>(g_Wouthi),
                                                      symaddr<__nv_bfloat16>(g_Woutlo),
                                                      2 * LAT_ * H_);
    k_split<<<(B_ * T_ * D_ + TPB - 1) / TPB, TPB>>>(x, symaddr<__nv_bfloat16>(g_x_hi),
                                                     symaddr<__nv_bfloat16>(g_x_lo),
                                                     B_ * T_ * D_);
    k_split_w1<<<(H2_ * H_ + TPB - 1) / TPB, TPB>>>(W1);
    k_tprep<<<(B_ * T_ + TPB - 1) / TPB, TPB>>>(ts);
    k_reset<<<(B_ * H_ + TPB - 1) / TPB, TPB>>>();

    k_persist<<<NCTA, NTHR>>>(bih, bhh, b1, b2, b3, bout, out);
}